// round 16
// baseline (speedup 1.0000x reference)
#include <cuda_runtime.h>
#include <cstdint>

#define N_PTS  65536
#define M_G    1024
#define KSEL   10
#define GRIDC  32
#define NCELL  (GRIDC * GRIDC)
#define CAP    192
#define BCAP   320
#define TPB    256
#define RTPB   256
#define POSINF (3.402823466e38f)

// Cholesky-affine form: h(x) = u0^2 + u1^2,  u0 = l00*x0 + l10*x1 + k0,
// u1 = l11*x1 + k1;  weight = exp2(-h); top-k largest weight == k SMALLEST h.
__device__ float4 g_c4[M_G];                    // dense coeffs
__device__ float  g_k1[M_G];
__device__ int    g_bcnt[NCELL];                // per-cell point count (self-zeroing)
__device__ int    g_bucket[NCELL * BCAP];       // per-cell point ids
__device__ int    g_ovfcnt;                     // bucket-overflow count (self-zeroing)
__device__ int    g_ovf[N_PTS];

// One pass over points: bin into per-cell buckets; first M_G threads also
// compute the Cholesky coefficients. g_bcnt/g_ovfcnt are zero on entry
// (module-load zero-init; render_fused re-zeroes them every invocation).
__global__ void __launch_bounds__(TPB) prep_bin_kernel(
    const float2* __restrict__ x,
    const float*  __restrict__ mus,
    const float*  __restrict__ covs)
{
    int t = blockIdx.x * blockDim.x + threadIdx.x;
    if (t < M_G) {
        float mu0 = __ldg(&mus[2 * t]), mu1 = __ldg(&mus[2 * t + 1]);
        float a = __ldg(&covs[4 * t + 0]);
        float b = __ldg(&covs[4 * t + 1]);   // symmetric
        float c = __ldg(&covs[4 * t + 3]);
        float det = a * c - b * b;
        const float L2E = 1.4426950408889634f;
        float sc = 0.5f * L2E / det;          // positive (Sigma SPD)
        float m00 = sc * c;
        float m01 = -sc * b;
        float m11 = sc * a;
        float l00 = sqrtf(m00);
        float l10 = m01 / l00;
        float l11 = sqrtf(m11 - l10 * l10);
        float k0  = -(l00 * mu0 + l10 * mu1);
        float k1  = -l11 * mu1;
        g_c4[t] = make_float4(l00, l10, k0, l11);
        g_k1[t] = k1;
    }
    float2 xv = __ldg(&x[t]);
    int cx = min(GRIDC - 1, (int)(xv.x * (float)GRIDC));
    int cy = min(GRIDC - 1, (int)(xv.y * (float)GRIDC));
    int cid = cy * GRIDC + cx;
    int slot = atomicAdd(&g_bcnt[cid], 1);
    if (slot < BCAP) g_bucket[cid * BCAP + slot] = t;
    else { int o = atomicAdd(&g_ovfcnt, 1); g_ovf[o] = t; }
}

__device__ __forceinline__ float ex2_approx(float x) {
    float r;
    asm("ex2.approx.ftz.f32 %0, %1;" : "=f"(r) : "f"(x));
    return r;
}

// Depth-2 branchless sorted insert into ASCENDING top[0..9] (keep 10 smallest).
__device__ __forceinline__ void siftf(float top[KSEL], float h) {
    float mx[KSEL - 1];
    #pragma unroll
    for (int j = 1; j < KSEL; ++j) mx[j - 1] = fmaxf(h, top[j - 1]);
    #pragma unroll
    for (int j = 1; j < KSEL; ++j) top[j] = fminf(mx[j - 1], top[j]);
    top[0] = fminf(top[0], h);
}

// FUSED: block = cell. Stage 1 builds the cell candidate list in smem:
// exact corner hmax; rigorous interval hmin; T >= exact 10th-smallest hmax
// via 2-round RADIX SELECT on the monotone uint bits of hmax (h >= 0), then
// m-ordered ballot compaction. Stage 2 renders the cell's points with
// 4 LANES PER POINT (full 256-thread utilization; exact top-10 + lowest-m
// tie fill via warp-uniform group-min iteration). Block 0 handles
// bucket-overflow points. Blocks self-zero g_bcnt for graph replay.
__global__ void __launch_bounds__(RTPB, 5) render_fused(
    const float2* __restrict__ x,
    const float*  __restrict__ cols,
    float*        __restrict__ out)
{
    __shared__ float4 sc4[CAP];
    __shared__ float2 sk [CAP];
    __shared__ int    shist[256];
    __shared__ int    sres[2];           // [bin, residual rank]
    __shared__ int    swn[8];
    int tid  = threadIdx.x;
    int wid  = tid >> 5;
    int lane = tid & 31;
    int cid  = blockIdx.x;

    const float csz = 1.0f / GRIDC;
    float x0a = (float)(cid & (GRIDC - 1)) * csz;
    float x1a = (float)(cid >> 5) * csz;
    float x0b = x0a + csz, x1b = x1a + csz;
    float ccx = x0a + 0.5f * csz, ccy = x1a + 0.5f * csz;
    float hx = 0.5f * csz;

    // ---- stage 1a: hmax (exact corner max) + hmin (rigorous) for 4/thread ----
    float hmx[4], hmn[4];
    #pragma unroll
    for (int r = 0; r < 4; ++r) {
        int m = wid * 128 + r * 32 + lane;
        float4 c = __ldg(&g_c4[m]);
        float k1 = __ldg(&g_k1[m]);
        float A0 = c.x * x0a, A1 = c.x * x0b;
        float B0 = fmaf(c.y, x1a, c.z), B1 = fmaf(c.y, x1b, c.z);
        float C0 = fmaf(c.w, x1a, k1),  C1 = fmaf(c.w, x1b, k1);
        float m0 = fmaxf(fabsf(A0 + B0), fabsf(A1 + B0));
        float m1 = fmaxf(fabsf(A0 + B1), fabsf(A1 + B1));
        hmx[r] = fmaxf(fmaf(m0, m0, C0 * C0), fmaf(m1, m1, C1 * C1));
        float u0c = fmaf(c.x, ccx, fmaf(c.y, ccy, c.z));
        float u1c = fmaf(c.w, ccy, k1);
        float r0 = (fabsf(c.x) + fabsf(c.y)) * hx;
        float r1 = fabsf(c.w) * hx;
        float lo0 = fmaxf(fabsf(u0c) - r0, 0.0f);
        float lo1 = fmaxf(fabsf(u1c) - r1, 0.0f);
        hmn[r] = fmaf(lo0, lo0, lo1 * lo1);
    }

    // ---- stage 1b: radix-select an upper bound T >= exact 10th-smallest hmax.
    unsigned key[4];
    #pragma unroll
    for (int r = 0; r < 4; ++r) key[r] = __float_as_uint(hmx[r]);

    auto scan_select = [&](int k) {
        if (wid == 0) {
            int b0 = lane * 8;
            int loc[8]; int sum = 0;
            #pragma unroll
            for (int j = 0; j < 8; ++j) { loc[j] = shist[b0 + j]; sum += loc[j]; }
            int pre = sum;
            #pragma unroll
            for (int d = 1; d < 32; d <<= 1) {
                int o = __shfl_up_sync(0xFFFFFFFFu, pre, d);
                if (lane >= d) pre += o;
            }
            int excl = pre - sum;
            bool has = (excl < k) && (pre >= k);
            unsigned bal = __ballot_sync(0xFFFFFFFFu, has);
            int src = __ffs((int)bal) - 1;
            if (lane == src) {
                int c = excl, bb = 0;
                #pragma unroll
                for (int j = 0; j < 8; ++j) {
                    bool hit = (c + loc[j] >= k);
                    if (!hit) c += loc[j]; else { bb = b0 + j; break; }
                }
                sres[0] = bb;
                sres[1] = k - c;     // residual rank inside bin bb
            }
        }
    };

    // round 1: bins = key >> 24
    shist[tid] = 0;
    __syncthreads();
    #pragma unroll
    for (int r = 0; r < 4; ++r) atomicAdd(&shist[key[r] >> 24], 1);
    __syncthreads();
    scan_select(KSEL);
    __syncthreads();
    int B1 = sres[0], k2 = sres[1];

    // round 2: among keys with top byte == B1, bins = (key >> 16) & 255
    shist[tid] = 0;
    __syncthreads();
    #pragma unroll
    for (int r = 0; r < 4; ++r)
        if ((int)(key[r] >> 24) == B1) atomicAdd(&shist[(key[r] >> 16) & 255u], 1);
    __syncthreads();
    scan_select(k2);
    __syncthreads();
    int B2 = sres[0];

    unsigned tbits = ((unsigned)B1 << 24) | ((unsigned)B2 << 16) | 0xFFFFu;
    float T = __uint_as_float(tbits);        // >= exact 10th-smallest hmax
    T = T * 1.001f + 1e-4f;                  // fp-safety margin (inflate)

    // ---- stage 1c: m-ordered ballot compaction into smem ----
    unsigned bm[4];
    #pragma unroll
    for (int r = 0; r < 4; ++r) {
        bool f = (hmn[r] * 0.999f - 1e-4f) <= T;    // fp-safety (deflate)
        bm[r] = __ballot_sync(0xFFFFFFFFu, f);
    }
    if (lane == 0)
        swn[wid] = __popc(bm[0]) + __popc(bm[1]) + __popc(bm[2]) + __popc(bm[3]);
    __syncthreads();
    int base = 0, n = 0;
    #pragma unroll
    for (int w = 0; w < 8; ++w) { if (w < wid) base += swn[w]; n += swn[w]; }
    bool fb = (n > CAP);                     // candidate overflow -> dense path
    if (!fb) {
        int off = base;
        #pragma unroll
        for (int r = 0; r < 4; ++r) {
            if ((bm[r] >> lane) & 1u) {
                int idx = off + __popc(bm[r] & ((1u << lane) - 1u));
                int m = wid * 128 + r * 32 + lane;
                sc4[idx] = __ldg(&g_c4[m]);
                sk [idx] = make_float2(__ldg(&g_k1[m]), __int_as_float(m));
            }
            off += __popc(bm[r]);
        }
    }
    __syncthreads();

    // ---- stage 2: render this cell's points, 4 lanes per point ----
    int pcnt = min(g_bcnt[cid], BCAP);
    int s = tid & 3;
    int ncand = fb ? M_G : n;
    int nl = (ncand - s + 3) >> 2;           // entries j==s (mod 4); ncand >= 10 > s

    #pragma unroll 1
    for (int pb = 0; pb < pcnt; pb += RTPB / 4) {
        int idx = pb + (tid >> 2);
        bool act = (idx < pcnt);
        if (__ballot_sync(0xFFFFFFFFu, act) == 0u) continue;   // warp-uniform skip
        int p = g_bucket[cid * BCAP + (act ? idx : 0)];
        float2 xv = __ldg(&x[p]);
        int mynl = act ? nl : 0;

        auto evalh = [&](const float4 c, float k1) -> float {
            float u0 = fmaf(c.x, xv.x, fmaf(c.y, xv.y, c.z));
            float u1 = fmaf(c.w, xv.y, k1);
            return fmaf(u0, u0, u1 * u1);
        };

        float top[KSEL];
        #pragma unroll
        for (int j = 0; j < KSEL; ++j) top[j] = POSINF;

        // pass 1: sift candidates (lane s covers entries 4j+s)
        #pragma unroll 2
        for (int j = 0; j < mynl; ++j) {
            int e = 4 * j + s;
            float4 c; float k1;
            if (fb) { c = __ldg(&g_c4[e]); k1 = __ldg(&g_k1[e]); }
            else    { c = sc4[e];          k1 = sk[e].x;         }
            siftf(top, evalh(c, k1));
        }

        // merge the 4 lane lists -> exact 10 smallest
        #pragma unroll
        for (int st = 1; st <= 2; st <<= 1) {
            float cur[KSEL];
            #pragma unroll
            for (int j = 0; j < KSEL; ++j) cur[j] = top[j];
            #pragma unroll
            for (int j = 0; j < KSEL; ++j)
                siftf(top, __shfl_xor_sync(0xFFFFFFFFu, cur[j], st));
        }
        float t = top[KSEL - 1];             // exact 10th-smallest h

        // pass 2: accumulate h < t; collect h == t ties (ascending m per lane)
        float r0 = 0.f, r1 = 0.f, r2 = 0.f, den = 0.f;
        int ltc = 0, eqc = 0;
        int t0 = 0x7FFFFFFF, t1 = 0x7FFFFFFF, t2 = 0x7FFFFFFF, t3 = 0x7FFFFFFF;

        auto acc = [&](int m, float h) {
            float v = ex2_approx(-h);
            r0 = fmaf(v, __ldg(&cols[3 * m + 0]), r0);
            r1 = fmaf(v, __ldg(&cols[3 * m + 1]), r1);
            r2 = fmaf(v, __ldg(&cols[3 * m + 2]), r2);
            den += v;
        };

        #pragma unroll 1
        for (int j = 0; j < mynl; ++j) {
            int e = 4 * j + s;
            float4 c; float k1; int m;
            if (fb) { m = e; c = __ldg(&g_c4[e]); k1 = __ldg(&g_k1[e]); }
            else    { c = sc4[e]; float2 kk = sk[e];
                      k1 = kk.x; m = __float_as_int(kk.y); }
            float h = evalh(c, k1);
            if (h < t) { acc(m, h); ltc++; }
            else if (h == t) {
                if      (eqc == 0) t0 = m;
                else if (eqc == 1) t1 = m;
                else if (eqc == 2) t2 = m;
                else if (eqc == 3) t3 = m;
                eqc++;
            }
        }
        int myc = min(eqc, 4);

        // exact tie fill: repeatedly take the global (4-lane) min-m tie.
        // Exit is WARP-UNIFORM (ballot) so the full-mask shuffles stay convergent.
        int lt_tot = ltc;
        lt_tot += __shfl_xor_sync(0xFFFFFFFFu, lt_tot, 1);
        lt_tot += __shfl_xor_sync(0xFFFFFFFFu, lt_tot, 2);
        int keep = act ? (KSEL - lt_tot) : 0;     // >= 1 when active
        int ptr = 0;
        #pragma unroll 1
        for (int itr = 0; itr < KSEL; ++itr) {
            int mym = (ptr < myc)
                    ? ((ptr == 0) ? t0 : (ptr == 1) ? t1 : (ptr == 2) ? t2 : t3)
                    : 0x7FFFFFFF;
            int w = mym;
            w = min(w, __shfl_xor_sync(0xFFFFFFFFu, w, 1));
            w = min(w, __shfl_xor_sync(0xFFFFFFFFu, w, 2));
            bool want = (keep > 0) && (w != 0x7FFFFFFF);
            if (__ballot_sync(0xFFFFFFFFu, want) == 0u) break;   // uniform exit
            if (want) {
                if (mym == w) { acc(w, t); ptr++; }
                keep--;
            }
        }

        // group reduction + write
        #pragma unroll
        for (int st = 1; st <= 2; st <<= 1) {
            r0  += __shfl_xor_sync(0xFFFFFFFFu, r0,  st);
            r1  += __shfl_xor_sync(0xFFFFFFFFu, r1,  st);
            r2  += __shfl_xor_sync(0xFFFFFFFFu, r2,  st);
            den += __shfl_xor_sync(0xFFFFFFFFu, den, st);
        }

        if (act && s == 0) {
            float inv = 1.0f / (den + 1e-6f);
            out[3 * p + 0] = r0 * inv;
            out[3 * p + 1] = r1 * inv;
            out[3 * p + 2] = r2 * inv;
        }
    }

    // ---- self-zero bucket counter for the next graph replay ----
    __syncthreads();
    if (tid == 0) g_bcnt[cid] = 0;

    // ---- block 0: exact dense path for bucket-overflow points ----
    if (cid == 0) {
        int total = g_ovfcnt;
        for (int i = tid; i < total; i += RTPB) {
            int p = g_ovf[i];
            float2 xv = __ldg(&x[p]);
            auto evalh = [&](const float4 c, float k1) -> float {
                float u0 = fmaf(c.x, xv.x, fmaf(c.y, xv.y, c.z));
                float u1 = fmaf(c.w, xv.y, k1);
                return fmaf(u0, u0, u1 * u1);
            };
            float top[KSEL];
            #pragma unroll
            for (int j = 0; j < KSEL; ++j) top[j] = POSINF;
            for (int m = 0; m < M_G; ++m)
                siftf(top, evalh(__ldg(&g_c4[m]), __ldg(&g_k1[m])));
            float t = top[KSEL - 1];
            float r0 = 0.f, r1 = 0.f, r2 = 0.f, den = 0.f;
            int ltc = 0;
            for (int m = 0; m < M_G; ++m) {
                float h = evalh(__ldg(&g_c4[m]), __ldg(&g_k1[m]));
                if (h < t) {
                    float v = ex2_approx(-h);
                    r0 = fmaf(v, __ldg(&cols[3 * m + 0]), r0);
                    r1 = fmaf(v, __ldg(&cols[3 * m + 1]), r1);
                    r2 = fmaf(v, __ldg(&cols[3 * m + 2]), r2);
                    den += v; ltc++;
                }
            }
            int keep = KSEL - ltc;
            for (int m = 0; m < M_G && keep > 0; ++m) {   // ties ascending m
                float h = evalh(__ldg(&g_c4[m]), __ldg(&g_k1[m]));
                if (h == t) {
                    float v = ex2_approx(-h);
                    r0 = fmaf(v, __ldg(&cols[3 * m + 0]), r0);
                    r1 = fmaf(v, __ldg(&cols[3 * m + 1]), r1);
                    r2 = fmaf(v, __ldg(&cols[3 * m + 2]), r2);
                    den += v; keep--;
                }
            }
            float inv = 1.0f / (den + 1e-6f);
            out[3 * p + 0] = r0 * inv;
            out[3 * p + 1] = r1 * inv;
            out[3 * p + 2] = r2 * inv;
        }
        __syncthreads();
        if (tid == 0) g_ovfcnt = 0;
    }
}

extern "C" void kernel_launch(void* const* d_in, const int* in_sizes, int n_in,
                              void* d_out, int out_size) {
    const float* xx   = (const float*)d_in[0];   // [N, 2]
    const float* mus  = (const float*)d_in[1];   // [1, M, 2]
    const float* covs = (const float*)d_in[2];   // [1, M, 2, 2]
    const float* cols = (const float*)d_in[3];   // [1, M, 3]
    float* out = (float*)d_out;                  // [N, 3]

    prep_bin_kernel<<<N_PTS / TPB, TPB>>>((const float2*)xx, mus, covs);
    render_fused<<<NCELL, RTPB>>>((const float2*)xx, cols, out);
}

// round 17
// speedup vs baseline: 1.1952x; 1.1952x over previous
#include <cuda_runtime.h>
#include <cstdint>

#define N_PTS  65536
#define M_G    1024
#define KSEL   10
#define GRIDC  32
#define NCELL  (GRIDC * GRIDC)
#define CAP    192
#define BCAP   320
#define TPB    256
#define RTPB   256
#define POSINF (3.402823466e38f)

// Cholesky-affine form: h(x) = u0^2 + u1^2,  u0 = l00*x0 + l10*x1 + k0,
// u1 = l11*x1 + k1;  weight = exp2(-h); top-k largest weight == k SMALLEST h.
__device__ float4 g_c4[M_G];                    // dense coeffs
__device__ float  g_k1[M_G];
__device__ int    g_bcnt[NCELL];                // per-cell point count (self-zeroing)
__device__ int    g_bucket[NCELL * BCAP];       // per-cell point ids
__device__ int    g_ovfcnt;                     // bucket-overflow count (self-zeroing)
__device__ int    g_ovf[N_PTS];

// One pass over points: bin into per-cell buckets; first M_G threads also
// compute the Cholesky coefficients. g_bcnt/g_ovfcnt are zero on entry
// (module-load zero-init; render_fused re-zeroes them every invocation).
__global__ void __launch_bounds__(TPB) prep_bin_kernel(
    const float2* __restrict__ x,
    const float*  __restrict__ mus,
    const float*  __restrict__ covs)
{
    int t = blockIdx.x * blockDim.x + threadIdx.x;
    if (t < M_G) {
        float mu0 = __ldg(&mus[2 * t]), mu1 = __ldg(&mus[2 * t + 1]);
        float a = __ldg(&covs[4 * t + 0]);
        float b = __ldg(&covs[4 * t + 1]);   // symmetric
        float c = __ldg(&covs[4 * t + 3]);
        float det = a * c - b * b;
        const float L2E = 1.4426950408889634f;
        float sc = 0.5f * L2E / det;          // positive (Sigma SPD)
        float m00 = sc * c;
        float m01 = -sc * b;
        float m11 = sc * a;
        float l00 = sqrtf(m00);
        float l10 = m01 / l00;
        float l11 = sqrtf(m11 - l10 * l10);
        float k0  = -(l00 * mu0 + l10 * mu1);
        float k1  = -l11 * mu1;
        g_c4[t] = make_float4(l00, l10, k0, l11);
        g_k1[t] = k1;
    }
    float2 xv = __ldg(&x[t]);
    int cx = min(GRIDC - 1, (int)(xv.x * (float)GRIDC));
    int cy = min(GRIDC - 1, (int)(xv.y * (float)GRIDC));
    int cid = cy * GRIDC + cx;
    int slot = atomicAdd(&g_bcnt[cid], 1);
    if (slot < BCAP) g_bucket[cid * BCAP + slot] = t;
    else { int o = atomicAdd(&g_ovfcnt, 1); g_ovf[o] = t; }
}

__device__ __forceinline__ float ex2_approx(float x) {
    float r;
    asm("ex2.approx.ftz.f32 %0, %1;" : "=f"(r) : "f"(x));
    return r;
}

// Depth-2 branchless sorted insert into ASCENDING top[0..9] (keep 10 smallest).
__device__ __forceinline__ void siftf(float top[KSEL], float h) {
    float mx[KSEL - 1];
    #pragma unroll
    for (int j = 1; j < KSEL; ++j) mx[j - 1] = fmaxf(h, top[j - 1]);
    #pragma unroll
    for (int j = 1; j < KSEL; ++j) top[j] = fminf(mx[j - 1], top[j]);
    top[0] = fminf(top[0], h);
}

// FUSED: block = cell. Stage 1 builds the cell candidate list in smem:
// exact corner hmax; rigorous interval hmin; T >= exact 10th-smallest hmax
// via 2-round RADIX SELECT on the monotone uint bits of hmax (h >= 0), then
// m-ordered ballot compaction. Stage 2 renders the cell's points with
// 2 lanes per point; the pair-merge computes only t (the 10th-smallest) via
// the bitonic lower-half identity: t = max_i min(A[i], B[9-i]) for sorted
// ascending lane lists A, B — bit-exact same t as a full merge.
// Block 0 handles bucket-overflow points. Blocks self-zero g_bcnt for replay.
__global__ void __launch_bounds__(RTPB, 5) render_fused(
    const float2* __restrict__ x,
    const float*  __restrict__ cols,
    float*        __restrict__ out)
{
    __shared__ float4 sc4[CAP];
    __shared__ float2 sk [CAP];
    __shared__ int    shist[256];
    __shared__ int    sres[2];           // [bin, residual rank]
    __shared__ int    swn[8];
    int tid  = threadIdx.x;
    int wid  = tid >> 5;
    int lane = tid & 31;
    int cid  = blockIdx.x;

    const float csz = 1.0f / GRIDC;
    float x0a = (float)(cid & (GRIDC - 1)) * csz;
    float x1a = (float)(cid >> 5) * csz;
    float x0b = x0a + csz, x1b = x1a + csz;
    float ccx = x0a + 0.5f * csz, ccy = x1a + 0.5f * csz;
    float hx = 0.5f * csz;

    // ---- stage 1a: hmax (exact corner max) + hmin (rigorous) for 4/thread ----
    float hmx[4], hmn[4];
    #pragma unroll
    for (int r = 0; r < 4; ++r) {
        int m = wid * 128 + r * 32 + lane;
        float4 c = __ldg(&g_c4[m]);
        float k1 = __ldg(&g_k1[m]);
        float A0 = c.x * x0a, A1 = c.x * x0b;
        float B0 = fmaf(c.y, x1a, c.z), B1 = fmaf(c.y, x1b, c.z);
        float C0 = fmaf(c.w, x1a, k1),  C1 = fmaf(c.w, x1b, k1);
        float m0 = fmaxf(fabsf(A0 + B0), fabsf(A1 + B0));
        float m1 = fmaxf(fabsf(A0 + B1), fabsf(A1 + B1));
        hmx[r] = fmaxf(fmaf(m0, m0, C0 * C0), fmaf(m1, m1, C1 * C1));
        float u0c = fmaf(c.x, ccx, fmaf(c.y, ccy, c.z));
        float u1c = fmaf(c.w, ccy, k1);
        float r0 = (fabsf(c.x) + fabsf(c.y)) * hx;
        float r1 = fabsf(c.w) * hx;
        float lo0 = fmaxf(fabsf(u0c) - r0, 0.0f);
        float lo1 = fmaxf(fabsf(u1c) - r1, 0.0f);
        hmn[r] = fmaf(lo0, lo0, lo1 * lo1);
    }

    // ---- stage 1b: radix-select an upper bound T >= exact 10th-smallest hmax.
    unsigned key[4];
    #pragma unroll
    for (int r = 0; r < 4; ++r) key[r] = __float_as_uint(hmx[r]);

    auto scan_select = [&](int k) {
        if (wid == 0) {
            int b0 = lane * 8;
            int loc[8]; int sum = 0;
            #pragma unroll
            for (int j = 0; j < 8; ++j) { loc[j] = shist[b0 + j]; sum += loc[j]; }
            int pre = sum;
            #pragma unroll
            for (int d = 1; d < 32; d <<= 1) {
                int o = __shfl_up_sync(0xFFFFFFFFu, pre, d);
                if (lane >= d) pre += o;
            }
            int excl = pre - sum;
            bool has = (excl < k) && (pre >= k);
            unsigned bal = __ballot_sync(0xFFFFFFFFu, has);
            int src = __ffs((int)bal) - 1;
            if (lane == src) {
                int c = excl, bb = 0;
                #pragma unroll
                for (int j = 0; j < 8; ++j) {
                    bool hit = (c + loc[j] >= k);
                    if (!hit) c += loc[j]; else { bb = b0 + j; break; }
                }
                sres[0] = bb;
                sres[1] = k - c;     // residual rank inside bin bb
            }
        }
    };

    // round 1: bins = key >> 24
    shist[tid] = 0;
    __syncthreads();
    #pragma unroll
    for (int r = 0; r < 4; ++r) atomicAdd(&shist[key[r] >> 24], 1);
    __syncthreads();
    scan_select(KSEL);
    __syncthreads();
    int B1 = sres[0], k2 = sres[1];

    // round 2: among keys with top byte == B1, bins = (key >> 16) & 255
    shist[tid] = 0;
    __syncthreads();
    #pragma unroll
    for (int r = 0; r < 4; ++r)
        if ((int)(key[r] >> 24) == B1) atomicAdd(&shist[(key[r] >> 16) & 255u], 1);
    __syncthreads();
    scan_select(k2);
    __syncthreads();
    int B2 = sres[0];

    unsigned tbits = ((unsigned)B1 << 24) | ((unsigned)B2 << 16) | 0xFFFFu;
    float T = __uint_as_float(tbits);        // >= exact 10th-smallest hmax
    T = T * 1.001f + 1e-4f;                  // fp-safety margin (inflate)

    // ---- stage 1c: m-ordered ballot compaction into smem ----
    unsigned bm[4];
    #pragma unroll
    for (int r = 0; r < 4; ++r) {
        bool f = (hmn[r] * 0.999f - 1e-4f) <= T;    // fp-safety (deflate)
        bm[r] = __ballot_sync(0xFFFFFFFFu, f);
    }
    if (lane == 0)
        swn[wid] = __popc(bm[0]) + __popc(bm[1]) + __popc(bm[2]) + __popc(bm[3]);
    __syncthreads();
    int base = 0, n = 0;
    #pragma unroll
    for (int w = 0; w < 8; ++w) { if (w < wid) base += swn[w]; n += swn[w]; }
    bool fb = (n > CAP);                     // candidate overflow -> dense path
    if (!fb) {
        int off = base;
        #pragma unroll
        for (int r = 0; r < 4; ++r) {
            if ((bm[r] >> lane) & 1u) {
                int idx = off + __popc(bm[r] & ((1u << lane) - 1u));
                int m = wid * 128 + r * 32 + lane;
                sc4[idx] = __ldg(&g_c4[m]);
                sk [idx] = make_float2(__ldg(&g_k1[m]), __int_as_float(m));
            }
            off += __popc(bm[r]);
        }
    }
    __syncthreads();

    // ---- stage 2: render this cell's points, 2 lanes per point ----
    int pcnt = min(g_bcnt[cid], BCAP);
    int s = tid & 1;
    int ncand = fb ? M_G : n;
    int nl = (ncand - s + 1) >> 1;           // entries j==s (mod 2)

    #pragma unroll 1
    for (int pb = 0; pb < pcnt; pb += RTPB / 2) {
        int idx = pb + (tid >> 1);
        bool act = (idx < pcnt);
        if (__ballot_sync(0xFFFFFFFFu, act) == 0u) continue;   // warp-uniform skip
        int p = g_bucket[cid * BCAP + (act ? idx : 0)];
        float2 xv = __ldg(&x[p]);
        int mynl = act ? nl : 0;

        auto evalh = [&](const float4 c, float k1) -> float {
            float u0 = fmaf(c.x, xv.x, fmaf(c.y, xv.y, c.z));
            float u1 = fmaf(c.w, xv.y, k1);
            return fmaf(u0, u0, u1 * u1);
        };

        float top[KSEL];
        #pragma unroll
        for (int j = 0; j < KSEL; ++j) top[j] = POSINF;

        // pass 1: sift candidates (lane s covers entries 2j+s)
        #pragma unroll 2
        for (int j = 0; j < mynl; ++j) {
            int e = 2 * j + s;
            float4 c; float k1;
            if (fb) { c = __ldg(&g_c4[e]); k1 = __ldg(&g_k1[e]); }
            else    { c = sc4[e];          k1 = sk[e].x;         }
            siftf(top, evalh(c, k1));
        }

        // t = 10th-smallest of both lanes' lists, WITHOUT a full merge:
        // bitonic lower-half identity on sorted ascending A (=mine), B (=peer):
        //   lower-10 set = { min(A[i], B[9-i]) },  t = max of that set.
        float t;
        {
            float mx = -POSINF;
            #pragma unroll
            for (int j = 0; j < KSEL; ++j) {
                float ob = __shfl_xor_sync(0xFFFFFFFFu, top[KSEL - 1 - j], 1);
                mx = fmaxf(mx, fminf(top[j], ob));
            }
            t = mx;                          // exact 10th-smallest h
        }

        // pass 2: accumulate h < t; collect h == t ties (ascending m per lane)
        float r0 = 0.f, r1 = 0.f, r2 = 0.f, den = 0.f;
        int ltc = 0, eqc = 0;
        int t0 = 0x7FFFFFFF, t1 = 0x7FFFFFFF, t2 = 0x7FFFFFFF, t3 = 0x7FFFFFFF;

        auto acc = [&](int m, float h) {
            float v = ex2_approx(-h);
            r0 = fmaf(v, __ldg(&cols[3 * m + 0]), r0);
            r1 = fmaf(v, __ldg(&cols[3 * m + 1]), r1);
            r2 = fmaf(v, __ldg(&cols[3 * m + 2]), r2);
            den += v;
        };

        #pragma unroll 1
        for (int j = 0; j < mynl; ++j) {
            int e = 2 * j + s;
            float4 c; float k1; int m;
            if (fb) { m = e; c = __ldg(&g_c4[e]); k1 = __ldg(&g_k1[e]); }
            else    { c = sc4[e]; float2 kk = sk[e];
                      k1 = kk.x; m = __float_as_int(kk.y); }
            float h = evalh(c, k1);
            if (h < t) { acc(m, h); ltc++; }
            else if (h == t) {
                if      (eqc == 0) t0 = m;
                else if (eqc == 1) t1 = m;
                else if (eqc == 2) t2 = m;
                else if (eqc == 3) t3 = m;
                eqc++;
            }
        }
        int myc = min(eqc, 4);

        // exact tie fill: keep lowest-m ties until exactly 10 selected.
        // Fixed 4-iteration loop (no data-dependent break) -> convergent.
        int lt_o = __shfl_xor_sync(0xFFFFFFFFu, ltc, 1);
        int keep = KSEL - (ltc + lt_o);      // >= 1 when active
        int ptr = 0;
        #pragma unroll
        for (int itr = 0; itr < 4; ++itr) {
            int mym = (ptr == 0) ? t0 : (ptr == 1) ? t1 : (ptr == 2) ? t2 : t3;
            if (ptr >= myc) mym = 0x7FFFFFFF;
            int om = __shfl_xor_sync(0xFFFFFFFFu, mym, 1);
            int w = min(mym, om);
            if (keep > 0 && w != 0x7FFFFFFF) {
                if (mym == w) { acc(w, t); ptr++; }
                keep--;
            }
        }

        // pair reduction + write
        r0  += __shfl_xor_sync(0xFFFFFFFFu, r0,  1);
        r1  += __shfl_xor_sync(0xFFFFFFFFu, r1,  1);
        r2  += __shfl_xor_sync(0xFFFFFFFFu, r2,  1);
        den += __shfl_xor_sync(0xFFFFFFFFu, den, 1);

        if (act && s == 0) {
            float inv = 1.0f / (den + 1e-6f);
            out[3 * p + 0] = r0 * inv;
            out[3 * p + 1] = r1 * inv;
            out[3 * p + 2] = r2 * inv;
        }
    }

    // ---- self-zero bucket counter for the next graph replay ----
    __syncthreads();
    if (tid == 0) g_bcnt[cid] = 0;

    // ---- block 0: exact dense path for bucket-overflow points ----
    if (cid == 0) {
        int total = g_ovfcnt;
        for (int i = tid; i < total; i += RTPB) {
            int p = g_ovf[i];
            float2 xv = __ldg(&x[p]);
            auto evalh = [&](const float4 c, float k1) -> float {
                float u0 = fmaf(c.x, xv.x, fmaf(c.y, xv.y, c.z));
                float u1 = fmaf(c.w, xv.y, k1);
                return fmaf(u0, u0, u1 * u1);
            };
            float top[KSEL];
            #pragma unroll
            for (int j = 0; j < KSEL; ++j) top[j] = POSINF;
            for (int m = 0; m < M_G; ++m)
                siftf(top, evalh(__ldg(&g_c4[m]), __ldg(&g_k1[m])));
            float t = top[KSEL - 1];
            float r0 = 0.f, r1 = 0.f, r2 = 0.f, den = 0.f;
            int ltc = 0;
            for (int m = 0; m < M_G; ++m) {
                float h = evalh(__ldg(&g_c4[m]), __ldg(&g_k1[m]));
                if (h < t) {
                    float v = ex2_approx(-h);
                    r0 = fmaf(v, __ldg(&cols[3 * m + 0]), r0);
                    r1 = fmaf(v, __ldg(&cols[3 * m + 1]), r1);
                    r2 = fmaf(v, __ldg(&cols[3 * m + 2]), r2);
                    den += v; ltc++;
                }
            }
            int keep = KSEL - ltc;
            for (int m = 0; m < M_G && keep > 0; ++m) {   // ties ascending m
                float h = evalh(__ldg(&g_c4[m]), __ldg(&g_k1[m]));
                if (h == t) {
                    float v = ex2_approx(-h);
                    r0 = fmaf(v, __ldg(&cols[3 * m + 0]), r0);
                    r1 = fmaf(v, __ldg(&cols[3 * m + 1]), r1);
                    r2 = fmaf(v, __ldg(&cols[3 * m + 2]), r2);
                    den += v; keep--;
                }
            }
            float inv = 1.0f / (den + 1e-6f);
            out[3 * p + 0] = r0 * inv;
            out[3 * p + 1] = r1 * inv;
            out[3 * p + 2] = r2 * inv;
        }
        __syncthreads();
        if (tid == 0) g_ovfcnt = 0;
    }
}

extern "C" void kernel_launch(void* const* d_in, const int* in_sizes, int n_in,
                              void* d_out, int out_size) {
    const float* xx   = (const float*)d_in[0];   // [N, 2]
    const float* mus  = (const float*)d_in[1];   // [1, M, 2]
    const float* covs = (const float*)d_in[2];   // [1, M, 2, 2]
    const float* cols = (const float*)d_in[3];   // [1, M, 3]
    float* out = (float*)d_out;                  // [N, 3]

    prep_bin_kernel<<<N_PTS / TPB, TPB>>>((const float2*)xx, mus, covs);
    render_fused<<<NCELL, RTPB>>>((const float2*)xx, cols, out);
}